// round 6
// baseline (speedup 1.0000x reference)
#include <cuda_runtime.h>
#include <cstdint>
typedef unsigned long long ull;

#define Bk 32
#define Sk 4096
#define Ik 64
#define Rk 1024
#define Ok 8

#define NB 128
#define BPB 8        // batches per block
#define JPB 32       // j per block
#define RPB 80       // bytes per k-pair row in rP (8 batches x 8B + 16B pad)
#define RED_PAR (64*33*4)
#define STP 1026     // stage pitch (floats)
#define SMEM_BYTES (JPB*STP*4)   // 131328; covers rP(40960)+red(2*8448)
#define SENT 0x7F800000u         // +inf sentinel; tanh output never inf

__device__ float g_pre[(size_t)Bk*Sk*Rk];
__device__ float g_rs [(size_t)Bk*Sk*Rk];
__device__ float g_rbuf[4*Bk*Rk];   // 4 slots, sentinel-initialized each launch

__device__ __forceinline__ void fma2(ull& a, ull b, ull c) {
    asm("fma.rn.f32x2 %0, %1, %2, %0;" : "+l"(a) : "l"(b), "l"(c));
}
__device__ __forceinline__ float hsum2(ull a) {
    unsigned l, h; asm("mov.b64 {%0,%1}, %2;" : "=r"(l), "=r"(h) : "l"(a));
    return __uint_as_float(l) + __uint_as_float(h);
}

__global__ void reset_kernel() {    // grid 128 x 256: sentinel-fill all slots
    unsigned* p = (unsigned*)g_rbuf;
    for (int i = blockIdx.x*blockDim.x + threadIdx.x; i < 4*Bk*Rk; i += 128*256)
        p[i] = SENT;
}
__global__ void nop_kernel() {}

// ---- Phase 1: pre = x @ W_in^T (f32x2 packed) ------------------------------
__global__ void __launch_bounds__(256) pre_kernel(const float* __restrict__ x,
                                                  const float* __restrict__ Win)
{
    __shared__ __align__(16) float xs[32*68];
    size_t rowBase = (size_t)blockIdx.x*32;
    for (int idx = threadIdx.x; idx < 32*64; idx += 256)
        xs[(idx>>6)*68 + (idx&63)] = x[(rowBase + (idx>>6))*64 + (idx&63)];
    __syncthreads();
    for (int jj = 0; jj < 4; jj++) {
        int j = jj*256 + threadIdx.x;
        ull w[32];
        const ull* wp = (const ull*)(Win + (size_t)j*64);
#pragma unroll
        for (int q = 0; q < 32; q++) w[q] = wp[q];
#pragma unroll 1
        for (int r = 0; r < 32; r++) {
            const ull* xr = (const ull*)&xs[r*68];
            ull a = 0, b = 0, c = 0, d = 0;
#pragma unroll
            for (int q = 0; q < 32; q += 4) {
                fma2(a, w[q], xr[q]);     fma2(b, w[q+1], xr[q+1]);
                fma2(c, w[q+2], xr[q+2]); fma2(d, w[q+3], xr[q+3]);
            }
            g_pre[(rowBase + r)*Rk + j] = (hsum2(a)+hsum2(b))+(hsum2(c)+hsum2(d));
        }
    }
}

// ---- Phase 2: persistent recurrence (sentinel-poll exchange) ---------------
__global__ void __launch_bounds__(256, 1) esn_main(const float* __restrict__ Wres)
{
    extern __shared__ __align__(16) float sm[];
    char* smc = (char*)sm;
    const int tid = threadIdx.x, wid = tid >> 5, lane = tid & 31;
    const int pb = blockIdx.x >> 5, pj = blockIdx.x & 31;
    const int b0 = pb*BPB, j0 = pj*JPB;
    const int kp0 = wid*64;                       // 64 k-pairs per warp

    // stage W slice, pull this thread's 64 (even,odd) weight pairs into regs
    for (int jl = 0; jl < JPB; jl++) {
        const float* src = Wres + (size_t)(j0 + jl)*Rk;
        for (int k = tid; k < Rk; k += 256) sm[jl*STP + k] = src[k];
    }
    __syncthreads();
    ull w2[64];
    {
        const ull* ws = (const ull*)(sm + lane*STP);
#pragma unroll
        for (int u = 0; u < 64; u++) w2[u] = ws[kp0 + u];
    }
    __syncthreads();

    char* rP   = smc;                              // [512 kp][RPB]
    char* redb = smc + 512*RPB;                    // 2 x [64][33] floats

    const size_t myoff = (size_t)(b0 + wid)*Rk + (j0 + lane);  // epilogue addr

    for (int t = 0; t < Sk; t++) {
        float preval = g_pre[((size_t)(b0 + wid)*Sk + t)*Rk + (j0 + lane)];

        if (t > 0) {
            // poll+stage: acquire-load the 8 float4s until no sentinel word
            const float4* src = (const float4*)(g_rbuf + (size_t)((t-1)&3)*(Bk*Rk));
            const int fi = wid*32 + lane;          // float4 idx in a batch row
            float4 v[8];
            for (;;) {
                unsigned bad = 0u;
#pragma unroll
                for (int bl = 0; bl < 8; bl++) {
                    const float4* p = src + (size_t)(b0 + bl)*(Rk/4) + fi;
                    asm volatile("ld.acquire.gpu.global.v4.f32 {%0,%1,%2,%3}, [%4];"
                                 : "=f"(v[bl].x), "=f"(v[bl].y),
                                   "=f"(v[bl].z), "=f"(v[bl].w)
                                 : "l"(p) : "memory");
                    bad |= (__float_as_uint(v[bl].x) == SENT) |
                           (__float_as_uint(v[bl].y) == SENT) |
                           (__float_as_uint(v[bl].z) == SENT) |
                           (__float_as_uint(v[bl].w) == SENT);
                }
                if (!bad) break;
            }
#pragma unroll
            for (int bp = 0; bp < 4; bp++) {
                float4 va = v[2*bp], vb = v[2*bp + 1];
                *(float4*)(rP + (size_t)(kp0 + 2*lane    )*RPB + bp*16) =
                    make_float4(va.x, va.y, vb.x, vb.y);
                *(float4*)(rP + (size_t)(kp0 + 2*lane + 1)*RPB + bp*16) =
                    make_float4(va.z, va.w, vb.z, vb.w);
            }
        } else {
            float4 z = make_float4(0.f, 0.f, 0.f, 0.f);
#pragma unroll
            for (int bp = 0; bp < 4; bp++) {
                *(float4*)(rP + (size_t)(kp0 + 2*lane    )*RPB + bp*16) = z;
                *(float4*)(rP + (size_t)(kp0 + 2*lane + 1)*RPB + bp*16) = z;
            }
        }
        __syncwarp();

        ull a0=0,a1=0,a2=0,a3=0,a4=0,a5=0,a6=0,a7=0;
        const char* rb = rP + (size_t)kp0*RPB;
#pragma unroll
        for (int u = 0; u < 64; u++) {
            const ulonglong2* rp = (const ulonglong2*)(rb + u*RPB);
            ulonglong2 q0 = rp[0], q1 = rp[1], q2 = rp[2], q3 = rp[3];
            ull w = w2[u];
            fma2(a0, w, q0.x); fma2(a1, w, q0.y);
            fma2(a2, w, q1.x); fma2(a3, w, q1.y);
            fma2(a4, w, q2.x); fma2(a5, w, q2.y);
            fma2(a6, w, q3.x); fma2(a7, w, q3.y);
        }
        float* red = (float*)(redb + (t & 1)*RED_PAR);
        red[(wid*8+0)*33+lane] = hsum2(a0); red[(wid*8+1)*33+lane] = hsum2(a1);
        red[(wid*8+2)*33+lane] = hsum2(a2); red[(wid*8+3)*33+lane] = hsum2(a3);
        red[(wid*8+4)*33+lane] = hsum2(a4); red[(wid*8+5)*33+lane] = hsum2(a5);
        red[(wid*8+6)*33+lane] = hsum2(a6); red[(wid*8+7)*33+lane] = hsum2(a7);
        __syncthreads();             // single block-wide sync per step

        {   // epilogue: thread (wid=batch-lane, lane=j)
            float s = preval;
#pragma unroll
            for (int kc = 0; kc < 8; kc++) s += red[(kc*8 + wid)*33 + lane];
            float e = __expf(2.f*fabsf(s));
            float rv = copysignf(1.f - __fdividef(2.f, e + 1.f), s);

            // sentinel-fill slot t+2 (safe: all same-pb blocks finished t-1,
            // so slot (t-2)&3 == (t+2)&3 has no remaining readers)
            if (t + 2 < Sk)
                *(unsigned*)&g_rbuf[(size_t)((t+2)&3)*(Bk*Rk) + myoff] = SENT;

            // data store IS the release (orders the sentinel store too)
            if (t < Sk - 1) {
                float* p = &g_rbuf[(size_t)(t&3)*(Bk*Rk) + myoff];
                asm volatile("st.release.gpu.global.f32 [%0], %1;"
                             :: "l"(p), "f"(rv) : "memory");
            }
            // DRAM-destined history store, off the release path
            g_rs[((size_t)(b0 + wid)*Sk + t)*Rk + (j0 + lane)] = rv;
        }
    }
}

// ---- Phase 3: out = [x, rs] @ W_out^T --------------------------------------
__global__ void __launch_bounds__(256) out_kernel(const float* __restrict__ x,
                                                  const float* __restrict__ Wout,
                                                  float* __restrict__ out)
{
    __shared__ float ws[Ok*1088];
    for (int idx = threadIdx.x; idx < Ok*1088; idx += 256) ws[idx] = Wout[idx];
    __syncthreads();
    int warp = threadIdx.x >> 5, lane = threadIdx.x & 31;
    for (size_t row = (size_t)blockIdx.x*8 + warp; row < (size_t)Bk*Sk;
         row += (size_t)gridDim.x*8) {
        const float* xr = x + row*Ik;
        const float* rr = g_rs + row*Rk;
        float acc[8] = {0,0,0,0,0,0,0,0};
#pragma unroll
        for (int q = 0; q < 2; q++) {
            int k = q*32 + lane; float f = xr[k];
#pragma unroll
            for (int o = 0; o < 8; o++) acc[o] = fmaf(f, ws[o*1088 + k], acc[o]);
        }
#pragma unroll 4
        for (int q = 0; q < 32; q++) {
            int k = q*32 + lane; float f = rr[k];
#pragma unroll
            for (int o = 0; o < 8; o++) acc[o] = fmaf(f, ws[o*1088 + 64 + k], acc[o]);
        }
#pragma unroll
        for (int o = 0; o < 8; o++)
#pragma unroll
            for (int off = 16; off; off >>= 1)
                acc[o] += __shfl_xor_sync(0xffffffffu, acc[o], off);
        if (lane == 0)
#pragma unroll
            for (int o = 0; o < 8; o++) out[row*Ok + o] = acc[o];
    }
}

extern "C" void kernel_launch(void* const* d_in, const int* in_sizes, int n_in,
                              void* d_out, int out_size)
{
    (void)in_sizes; (void)n_in; (void)out_size;
    const float* x    = (const float*)d_in[0];
    const float* Win  = (const float*)d_in[1];
    const float* Wres = (const float*)d_in[2];
    const float* Wout = (const float*)d_in[3];
    cudaFuncSetAttribute(esn_main, cudaFuncAttributeMaxDynamicSharedMemorySize,
                         SMEM_BYTES);
    reset_kernel<<<128, 256>>>();
    pre_kernel<<<(Bk*Sk)/32, 256>>>(x, Win);
    nop_kernel<<<1, 32>>>();    // harness poison-fill is idx 0; these make
    nop_kernel<<<1, 32>>>();    // esn_main process-launch idx 5 for ncu -s 5
    esn_main<<<NB, 256, SMEM_BYTES>>>(Wres);
    out_kernel<<<2048, 256>>>(x, Wout, (float*)d_out);
}

// round 7
// speedup vs baseline: 1.5150x; 1.5150x over previous
#include <cuda_runtime.h>
#include <cstdint>
typedef unsigned long long ull;

#define Bk 32
#define Sk 4096
#define Ik 64
#define Rk 1024
#define Ok 8

#define NB 128
#define BPB 8        // batches per block
#define JPB 32       // j per block
#define RPB 80       // bytes per k-pair row in rP (8 batches x 8B + 16B pad)
#define STP 1026     // stage pitch (floats)
#define SMEM_BYTES (JPB*STP*4)   // 131328; covers rP(40960)+red(8448)

__device__ float g_pre[(size_t)Bk*Sk*Rk];
__device__ float g_rs [(size_t)Bk*Sk*Rk];
__device__ float g_rbuf[2*Bk*Rk];
__device__ unsigned g_flags[NB*32];

__device__ __forceinline__ void fma2(ull& a, ull b, ull c) {
    asm("fma.rn.f32x2 %0, %1, %2, %0;" : "+l"(a) : "l"(b), "l"(c));
}
__device__ __forceinline__ float hsum2(ull a) {
    unsigned l, h; asm("mov.b64 {%0,%1}, %2;" : "=r"(l), "=r"(h) : "l"(a));
    return __uint_as_float(l) + __uint_as_float(h);
}

__global__ void reset_kernel() {
    if (threadIdx.x < NB) g_flags[threadIdx.x*32] = 0u;
}
__global__ void nop_kernel() {}

// ---- Phase 1: pre = x @ W_in^T (f32x2 packed) ------------------------------
__global__ void __launch_bounds__(256) pre_kernel(const float* __restrict__ x,
                                                  const float* __restrict__ Win)
{
    __shared__ __align__(16) float xs[32*68];
    size_t rowBase = (size_t)blockIdx.x*32;
    for (int idx = threadIdx.x; idx < 32*64; idx += 256)
        xs[(idx>>6)*68 + (idx&63)] = x[(rowBase + (idx>>6))*64 + (idx&63)];
    __syncthreads();
    for (int jj = 0; jj < 4; jj++) {
        int j = jj*256 + threadIdx.x;
        ull w[32];
        const ull* wp = (const ull*)(Win + (size_t)j*64);
#pragma unroll
        for (int q = 0; q < 32; q++) w[q] = wp[q];
#pragma unroll 1
        for (int r = 0; r < 32; r++) {
            const ull* xr = (const ull*)&xs[r*68];
            ull a = 0, b = 0, c = 0, d = 0;
#pragma unroll
            for (int q = 0; q < 32; q += 4) {
                fma2(a, w[q], xr[q]);     fma2(b, w[q+1], xr[q+1]);
                fma2(c, w[q+2], xr[q+2]); fma2(d, w[q+3], xr[q+3]);
            }
            g_pre[(rowBase + r)*Rk + j] = (hsum2(a)+hsum2(b))+(hsum2(c)+hsum2(d));
        }
    }
}

// ---- Phase 2: persistent recurrence (R4 exchange structure) ----------------
__global__ void __launch_bounds__(256, 1) esn_main(const float* __restrict__ Wres)
{
    extern __shared__ __align__(16) float sm[];
    char* smc = (char*)sm;
    const int tid = threadIdx.x, wid = tid >> 5, lane = tid & 31;
    const int pb = blockIdx.x >> 5, pj = blockIdx.x & 31;
    const int b0 = pb*BPB, j0 = pj*JPB;
    const int kp0 = wid*64;                       // 64 k-pairs per warp

    // stage W slice, pull this thread's 64 (even,odd) weight pairs into regs
    for (int jl = 0; jl < JPB; jl++) {
        const float* src = Wres + (size_t)(j0 + jl)*Rk;
        for (int k = tid; k < Rk; k += 256) sm[jl*STP + k] = src[k];
    }
    __syncthreads();
    ull w2[64];
    {
        const ull* ws = (const ull*)(sm + lane*STP);
#pragma unroll
        for (int u = 0; u < 64; u++) w2[u] = ws[kp0 + u];
    }
    __syncthreads();

    char*  rP  = smc;                              // [512 kp][RPB]
    float* red = (float*)(smc + 512*RPB);          // [64][33]

    for (int t = 0; t < Sk; t++) {
        float preval = g_pre[((size_t)(b0 + wid)*Sk + t)*Rk + (j0 + lane)];

        if (t > 0) {   // wait for this warp's 4 producer blocks (same pb)
            const unsigned* fp = g_flags + (size_t)(pb*32 + (wid*4 + (lane & 3)))*32;
            unsigned v;
            do { asm volatile("ld.acquire.gpu.global.u32 %0, [%1];"
                              : "=r"(v) : "l"(fp) : "memory"); } while (v < (unsigned)t);
        }
        __syncwarp();

        if (t > 0) {   // stage r chunk as k-pairs: rP[kp] = 8 batches x (even,odd)
            const float2* src = (const float2*)(g_rbuf + (size_t)((t-1)&1)*(Bk*Rk));
#pragma unroll
            for (int kk = 0; kk < 2; kk++) {
                int kpx = kp0 + kk*32 + lane;
#pragma unroll
                for (int bl = 0; bl < BPB; bl++)
                    *(float2*)(rP + (size_t)kpx*RPB + bl*8) =
                        src[(size_t)(b0 + bl)*(Rk/2) + kpx];
            }
        } else {
            float2 z = make_float2(0.f, 0.f);
#pragma unroll
            for (int kk = 0; kk < 2; kk++) {
                int kpx = kp0 + kk*32 + lane;
#pragma unroll
                for (int bl = 0; bl < BPB; bl++)
                    *(float2*)(rP + (size_t)kpx*RPB + bl*8) = z;
            }
        }
        __syncwarp();

        ull a0=0,a1=0,a2=0,a3=0,a4=0,a5=0,a6=0,a7=0;
        const char* rb = rP + (size_t)kp0*RPB;
#pragma unroll
        for (int u = 0; u < 64; u++) {
            const ulonglong2* rp = (const ulonglong2*)(rb + u*RPB);
            ulonglong2 q0 = rp[0], q1 = rp[1], q2 = rp[2], q3 = rp[3];
            ull w = w2[u];
            fma2(a0, w, q0.x); fma2(a1, w, q0.y);
            fma2(a2, w, q1.x); fma2(a3, w, q1.y);
            fma2(a4, w, q2.x); fma2(a5, w, q2.y);
            fma2(a6, w, q3.x); fma2(a7, w, q3.y);
        }
        red[(wid*8+0)*33+lane] = hsum2(a0); red[(wid*8+1)*33+lane] = hsum2(a1);
        red[(wid*8+2)*33+lane] = hsum2(a2); red[(wid*8+3)*33+lane] = hsum2(a3);
        red[(wid*8+4)*33+lane] = hsum2(a4); red[(wid*8+5)*33+lane] = hsum2(a5);
        red[(wid*8+6)*33+lane] = hsum2(a6); red[(wid*8+7)*33+lane] = hsum2(a7);
        __syncthreads();

        float rv;
        {   // epilogue: thread (wid=batch-lane, lane=j)
            float s = preval;
#pragma unroll
            for (int kc = 0; kc < 8; kc++) s += red[(kc*8 + wid)*33 + lane];
            float e = __expf(2.f*fabsf(s));
            rv = copysignf(1.f - __fdividef(2.f, e + 1.f), s);
            if (t < Sk - 1)
                g_rbuf[(size_t)(t&1)*(Bk*Rk) + (size_t)(b0 + wid)*Rk + (j0 + lane)] = rv;
        }
        __syncthreads();

        if (tid == 0 && t < Sk - 1) {
            unsigned nv = (unsigned)(t + 1);
            asm volatile("st.release.gpu.global.u32 [%0], %1;"
                         :: "l"(g_flags + (size_t)blockIdx.x*32), "r"(nv) : "memory");
        }
        // DRAM-destined history store, off the release path
        g_rs[((size_t)(b0 + wid)*Sk + t)*Rk + (j0 + lane)] = rv;
    }
}

// ---- Phase 3: out = [x, rs] @ W_out^T --------------------------------------
__global__ void __launch_bounds__(256) out_kernel(const float* __restrict__ x,
                                                  const float* __restrict__ Wout,
                                                  float* __restrict__ out)
{
    __shared__ float ws[Ok*1088];
    for (int idx = threadIdx.x; idx < Ok*1088; idx += 256) ws[idx] = Wout[idx];
    __syncthreads();
    int warp = threadIdx.x >> 5, lane = threadIdx.x & 31;
    for (size_t row = (size_t)blockIdx.x*8 + warp; row < (size_t)Bk*Sk;
         row += (size_t)gridDim.x*8) {
        const float* xr = x + row*Ik;
        const float* rr = g_rs + row*Rk;
        float acc[8] = {0,0,0,0,0,0,0,0};
#pragma unroll
        for (int q = 0; q < 2; q++) {
            int k = q*32 + lane; float f = xr[k];
#pragma unroll
            for (int o = 0; o < 8; o++) acc[o] = fmaf(f, ws[o*1088 + k], acc[o]);
        }
#pragma unroll 4
        for (int q = 0; q < 32; q++) {
            int k = q*32 + lane; float f = rr[k];
#pragma unroll
            for (int o = 0; o < 8; o++) acc[o] = fmaf(f, ws[o*1088 + 64 + k], acc[o]);
        }
#pragma unroll
        for (int o = 0; o < 8; o++)
#pragma unroll
            for (int off = 16; off; off >>= 1)
                acc[o] += __shfl_xor_sync(0xffffffffu, acc[o], off);
        if (lane == 0)
#pragma unroll
            for (int o = 0; o < 8; o++) out[row*Ok + o] = acc[o];
    }
}

extern "C" void kernel_launch(void* const* d_in, const int* in_sizes, int n_in,
                              void* d_out, int out_size)
{
    (void)in_sizes; (void)n_in; (void)out_size;
    const float* x    = (const float*)d_in[0];
    const float* Win  = (const float*)d_in[1];
    const float* Wres = (const float*)d_in[2];
    const float* Wout = (const float*)d_in[3];
    cudaFuncSetAttribute(esn_main, cudaFuncAttributeMaxDynamicSharedMemorySize,
                         SMEM_BYTES);
    reset_kernel<<<1, 128>>>();
    pre_kernel<<<(Bk*Sk)/32, 256>>>(x, Win);
    nop_kernel<<<1, 32>>>();    // 2 harness pre-launches + reset + pre + nop
    esn_main<<<NB, 256, SMEM_BYTES>>>(Wres);   // -> process-launch idx 5 (ncu -s 5)
    out_kernel<<<2048, 256>>>(x, Wout, (float*)d_out);
}

// round 8
// speedup vs baseline: 1.5225x; 1.0049x over previous
#include <cuda_runtime.h>
#include <cstdint>
typedef unsigned long long ull;

#define Bk 32
#define Sk 4096
#define Ik 64
#define Rk 1024
#define Ok 8

#define NB 128
#define BPB 8        // batches per block
#define JPB 32       // j per block
#define RPB 80       // bytes per k-pair row in rP
#define STP 1026     // W staging pitch (floats)
#define SMEM_BYTES (JPB*STP*4)   // 131328

// persistent SMEM float offsets (inside the 131328B region, after staging)
#define RED_F   10240            // red[64][33]
#define XS_F    12352            // xs[8][66]
#define WIN_F   12880            // WinS[32][66]
#define WOR_F   14992            // WoutR[8][33]
#define WOX_F   15256            // WoutX[8][66]  (ends 15784 floats)

__device__ float g_rbuf[2*Bk*Rk];
__device__ unsigned g_flags[NB*32];

__device__ __forceinline__ void fma2(ull& a, ull b, ull c) {
    asm("fma.rn.f32x2 %0, %1, %2, %0;" : "+l"(a) : "l"(b), "l"(c));
}
__device__ __forceinline__ float hsum2(ull a) {
    unsigned l, h; asm("mov.b64 {%0,%1}, %2;" : "=r"(l), "=r"(h) : "l"(a));
    return __uint_as_float(l) + __uint_as_float(h);
}

__global__ void reset_kernel(float* out) {   // zero flags + output (atomics!)
    int i = blockIdx.x*blockDim.x + threadIdx.x;
    if (blockIdx.x == 0 && threadIdx.x < NB) g_flags[threadIdx.x*32] = 0u;
    for (int k = i; k < Bk*Sk*Ok; k += gridDim.x*blockDim.x) out[k] = 0.f;
}
__global__ void nop_kernel() {}

// ---------------------------------------------------------------------------
// Fused persistent kernel: pre-GEMM + recurrence + readout, no DRAM in loop.
// Block (pb,pj): batches [pb*8,+8) x j [pj*32,+32). R4 exchange (flags+rbuf).
// ---------------------------------------------------------------------------
__global__ void __launch_bounds__(256, 1) esn_main(const float* __restrict__ xg,
                                                   const float* __restrict__ Win,
                                                   const float* __restrict__ Wres,
                                                   const float* __restrict__ Wout,
                                                   float* __restrict__ out)
{
    extern __shared__ __align__(16) float sm[];
    char* smc = (char*)sm;
    const int tid = threadIdx.x, wid = tid >> 5, lane = tid & 31;
    const int pb = blockIdx.x >> 5, pj = blockIdx.x & 31;
    const int b0 = pb*BPB, j0 = pj*JPB;
    const int kp0 = wid*64;                       // 64 k-pairs per warp

    // ---- one-time: stage W_res slice, pull 64 weight pairs into registers
    for (int jl = 0; jl < JPB; jl++) {
        const float* src = Wres + (size_t)(j0 + jl)*Rk;
        for (int k = tid; k < Rk; k += 256) sm[jl*STP + k] = src[k];
    }
    __syncthreads();
    ull w2[64];
    {
        const ull* ws = (const ull*)(sm + lane*STP);
#pragma unroll
        for (int u = 0; u < 64; u++) w2[u] = ws[kp0 + u];
    }
    __syncthreads();

    // ---- persistent slices (region overlapped the staging buffer)
    float* WinS  = sm + WIN_F;   // [32][66]
    float* WoRS  = sm + WOR_F;   // [8][33]
    float* WoXS  = sm + WOX_F;   // [8][66]
    float* xs    = sm + XS_F;    // [8][66] per-step x rows (warp-private rows)
    float* red   = sm + RED_F;   // [64][33]
    char*  rP    = smc;          // [512 kp][RPB]
    for (int idx = tid; idx < 32*64; idx += 256)
        WinS[(idx>>6)*66 + (idx&63)] = Win[(size_t)(j0 + (idx>>6))*64 + (idx&63)];
    for (int idx = tid; idx < 8*32; idx += 256)
        WoRS[(idx>>5)*33 + (idx&31)] = Wout[(size_t)(idx>>5)*1088 + 64 + j0 + (idx&31)];
    for (int idx = tid; idx < 8*64; idx += 256)
        WoXS[(idx>>6)*66 + (idx&63)] = Wout[(size_t)(idx>>6)*1088 + (idx&63)];
    __syncthreads();

    // ---- preval for t=0 (stage x row, compute pre via SMEM Win slice)
    float preval;
    {
        *(float2*)(xs + wid*66 + 2*lane) =
            *(const float2*)(xg + ((size_t)(b0 + wid)*Sk + 0)*Ik + 2*lane);
        __syncwarp();
        const ull* xp = (const ull*)(xs + wid*66);
        const ull* wp = (const ull*)(WinS + lane*66);
        ull a = 0, b = 0;
#pragma unroll
        for (int ip = 0; ip < 32; ip += 2) { fma2(a, wp[ip], xp[ip]); fma2(b, wp[ip+1], xp[ip+1]); }
        preval = hsum2(a) + hsum2(b);
    }

    for (int t = 0; t < Sk; t++) {
        if (t > 0) {   // wait for this warp's 4 producer blocks (same pb)
            const unsigned* fp = g_flags + (size_t)(pb*32 + (wid*4 + (lane & 3)))*32;
            unsigned v;
            do { asm volatile("ld.acquire.gpu.global.u32 %0, [%1];"
                              : "=r"(v) : "l"(fp) : "memory"); } while (v < (unsigned)t);
        }
        __syncwarp();

        if (t > 0) {   // stage r chunk as k-pairs
            const float2* src = (const float2*)(g_rbuf + (size_t)((t-1)&1)*(Bk*Rk));
#pragma unroll
            for (int kk = 0; kk < 2; kk++) {
                int kpx = kp0 + kk*32 + lane;
#pragma unroll
                for (int bl = 0; bl < BPB; bl++)
                    *(float2*)(rP + (size_t)kpx*RPB + bl*8) =
                        src[(size_t)(b0 + bl)*(Rk/2) + kpx];
            }
        } else {
            float2 z = make_float2(0.f, 0.f);
#pragma unroll
            for (int kk = 0; kk < 2; kk++) {
                int kpx = kp0 + kk*32 + lane;
#pragma unroll
                for (int bl = 0; bl < BPB; bl++)
                    *(float2*)(rP + (size_t)kpx*RPB + bl*8) = z;
            }
        }
        __syncwarp();

        ull a0=0,a1=0,a2=0,a3=0,a4=0,a5=0,a6=0,a7=0;
        const char* rb = rP + (size_t)kp0*RPB;
#pragma unroll
        for (int u = 0; u < 64; u++) {
            const ulonglong2* rp = (const ulonglong2*)(rb + u*RPB);
            ulonglong2 q0 = rp[0], q1 = rp[1], q2 = rp[2], q3 = rp[3];
            ull w = w2[u];
            fma2(a0, w, q0.x); fma2(a1, w, q0.y);
            fma2(a2, w, q1.x); fma2(a3, w, q1.y);
            fma2(a4, w, q2.x); fma2(a5, w, q2.y);
            fma2(a6, w, q3.x); fma2(a7, w, q3.y);
        }
        red[(wid*8+0)*33+lane] = hsum2(a0); red[(wid*8+1)*33+lane] = hsum2(a1);
        red[(wid*8+2)*33+lane] = hsum2(a2); red[(wid*8+3)*33+lane] = hsum2(a3);
        red[(wid*8+4)*33+lane] = hsum2(a4); red[(wid*8+5)*33+lane] = hsum2(a5);
        red[(wid*8+6)*33+lane] = hsum2(a6); red[(wid*8+7)*33+lane] = hsum2(a7);
        __syncthreads();

        float rv;
        {   // epilogue: thread (wid=batch-lane, lane=j)
            float s = preval;
#pragma unroll
            for (int kc = 0; kc < 8; kc++) s += red[(kc*8 + wid)*33 + lane];
            float e = __expf(2.f*fabsf(s));
            rv = copysignf(1.f - __fdividef(2.f, e + 1.f), s);
            if (t < Sk - 1)
                g_rbuf[(size_t)(t&1)*(Bk*Rk) + (size_t)(b0 + wid)*Rk + (j0 + lane)] = rv;
        }
        __syncthreads();
        if (tid == 0 && t < Sk - 1) {
            unsigned nv = (unsigned)(t + 1);
            asm volatile("st.release.gpu.global.u32 [%0], %1;"
                         :: "l"(g_flags + (size_t)blockIdx.x*32), "r"(nv) : "memory");
        }

        // ================= post-release slack work =================
        // (a) readout partials over this block's 32 j
        {
            float myout = 0.f;
#pragma unroll
            for (int o = 0; o < 8; o++) {
                float p = rv * WoRS[o*33 + lane];
                p += __shfl_xor_sync(~0u, p, 16); p += __shfl_xor_sync(~0u, p, 8);
                p += __shfl_xor_sync(~0u, p, 4);  p += __shfl_xor_sync(~0u, p, 2);
                p += __shfl_xor_sync(~0u, p, 1);
                if (lane == o) myout = p;
            }
            if (lane < 8)
                atomicAdd(&out[((size_t)(b0 + wid)*Sk + t)*Ok + lane], myout);
            // x-part: block pj==o handles output o (uses xs of step t, still valid)
            if (pj < 8) {
                float p = xs[wid*66 + lane]      * WoXS[pj*66 + lane]
                        + xs[wid*66 + 32 + lane] * WoXS[pj*66 + 32 + lane];
                p += __shfl_xor_sync(~0u, p, 16); p += __shfl_xor_sync(~0u, p, 8);
                p += __shfl_xor_sync(~0u, p, 4);  p += __shfl_xor_sync(~0u, p, 2);
                p += __shfl_xor_sync(~0u, p, 1);
                if (lane == 0)
                    atomicAdd(&out[((size_t)(b0 + wid)*Sk + t)*Ok + pj], p);
            }
        }
        // (b) stage x(t+1) and precompute preval(t+1)
        if (t < Sk - 1) {
            *(float2*)(xs + wid*66 + 2*lane) =
                *(const float2*)(xg + ((size_t)(b0 + wid)*Sk + (t+1))*Ik + 2*lane);
            __syncwarp();
            const ull* xp = (const ull*)(xs + wid*66);
            const ull* wp = (const ull*)(WinS + lane*66);
            ull a = 0, b = 0;
#pragma unroll
            for (int ip = 0; ip < 32; ip += 2) { fma2(a, wp[ip], xp[ip]); fma2(b, wp[ip+1], xp[ip+1]); }
            preval = hsum2(a) + hsum2(b);
        }
    }
}

extern "C" void kernel_launch(void* const* d_in, const int* in_sizes, int n_in,
                              void* d_out, int out_size)
{
    (void)in_sizes; (void)n_in; (void)out_size;
    const float* x    = (const float*)d_in[0];
    const float* Win  = (const float*)d_in[1];
    const float* Wres = (const float*)d_in[2];
    const float* Wout = (const float*)d_in[3];
    cudaFuncSetAttribute(esn_main, cudaFuncAttributeMaxDynamicSharedMemorySize,
                         SMEM_BYTES);
    reset_kernel<<<512, 256>>>((float*)d_out);
    nop_kernel<<<1, 32>>>();     // 2 harness pre-launches + reset + 2 nops
    nop_kernel<<<1, 32>>>();     //   -> esn_main at process-launch idx 5 (ncu -s 5)
    esn_main<<<NB, 256, SMEM_BYTES>>>(x, Win, Wres, Wout, (float*)d_out);
}